// round 9
// baseline (speedup 1.0000x reference)
#include <cuda_runtime.h>

// DepthWiseConv1d: inputs [B=32, C=128, L=8192] fp32, weight [C,3], bias [C].
// out[b,c,l] = w0*x[l-1] + w1*x[l] + w2*x[l+1] + bias  (zero pad at l=-1, l=L)
//
// R5: ILP=4 — each thread processes 4 consecutive float4 (64B of a row).
// All interior neighbors come from registers; only 2 scalar halo loads per
// 64B (vs per 16B before). Front-batched loads give MLP~5 per thread.
// __stcs on stores (output never re-read).

#define L_LEN   8192
#define C_CH    128
#define CHUNK   16                 // floats per thread
#define L_CHK   (L_LEN / CHUNK)    // 512 chunks per row

__global__ __launch_bounds__(256) void dwconv1d_kernel(
    const float* __restrict__ x,
    const float* __restrict__ weight,   // [C, 3]
    const float* __restrict__ bias,     // [C]
    float* __restrict__ out,
    int total_chunks)                   // B*C*L_CHK
{
    int idx = blockIdx.x * blockDim.x + threadIdx.x;
    if (idx >= total_chunks) return;

    int lc  = idx & (L_CHK - 1);        // chunk index within row
    int row = idx >> 9;                 // idx / 512
    int c   = row & (C_CH - 1);         // channel

    const float* xrow = x + (size_t)row * L_LEN;
    int l = lc << 4;                    // first element of this thread's span

    // Front-batched vector loads: 4 independent LDG.128 (MLP_p1 >= 4)
    const float4* xv = reinterpret_cast<const float4*>(xrow + l);
    float4 v0 = xv[0];
    float4 v1 = xv[1];
    float4 v2 = xv[2];
    float4 v3 = xv[3];

    // Halo loads (one per 64B span; zero-padded at row edges)
    float left  = (l == 0)              ? 0.0f : __ldg(xrow + l - 1);
    float right = (l + CHUNK == L_LEN)  ? 0.0f : __ldg(xrow + l + CHUNK);

    float w0 = __ldg(weight + 3 * c + 0);
    float w1 = __ldg(weight + 3 * c + 1);
    float w2 = __ldg(weight + 3 * c + 2);
    float b  = __ldg(bias + c);

    float4 o0, o1, o2, o3;
    o0.x = fmaf(w0, left, fmaf(w1, v0.x, fmaf(w2, v0.y, b)));
    o0.y = fmaf(w0, v0.x, fmaf(w1, v0.y, fmaf(w2, v0.z, b)));
    o0.z = fmaf(w0, v0.y, fmaf(w1, v0.z, fmaf(w2, v0.w, b)));
    o0.w = fmaf(w0, v0.z, fmaf(w1, v0.w, fmaf(w2, v1.x, b)));

    o1.x = fmaf(w0, v0.w, fmaf(w1, v1.x, fmaf(w2, v1.y, b)));
    o1.y = fmaf(w0, v1.x, fmaf(w1, v1.y, fmaf(w2, v1.z, b)));
    o1.z = fmaf(w0, v1.y, fmaf(w1, v1.z, fmaf(w2, v1.w, b)));
    o1.w = fmaf(w0, v1.z, fmaf(w1, v1.w, fmaf(w2, v2.x, b)));

    o2.x = fmaf(w0, v1.w, fmaf(w1, v2.x, fmaf(w2, v2.y, b)));
    o2.y = fmaf(w0, v2.x, fmaf(w1, v2.y, fmaf(w2, v2.z, b)));
    o2.z = fmaf(w0, v2.y, fmaf(w1, v2.z, fmaf(w2, v2.w, b)));
    o2.w = fmaf(w0, v2.z, fmaf(w1, v2.w, fmaf(w2, v3.x, b)));

    o3.x = fmaf(w0, v2.w, fmaf(w1, v3.x, fmaf(w2, v3.y, b)));
    o3.y = fmaf(w0, v3.x, fmaf(w1, v3.y, fmaf(w2, v3.z, b)));
    o3.z = fmaf(w0, v3.y, fmaf(w1, v3.z, fmaf(w2, v3.w, b)));
    o3.w = fmaf(w0, v3.z, fmaf(w1, v3.w, fmaf(w2, right, b)));

    float4* ov = reinterpret_cast<float4*>(out + (size_t)row * L_LEN + l);
    __stcs(ov + 0, o0);
    __stcs(ov + 1, o1);
    __stcs(ov + 2, o2);
    __stcs(ov + 3, o3);
}

extern "C" void kernel_launch(void* const* d_in, const int* in_sizes, int n_in,
                              void* d_out, int out_size)
{
    const float* x      = (const float*)d_in[0];   // [32,128,8192]
    const float* weight = (const float*)d_in[1];   // [128,3]
    const float* bias   = (const float*)d_in[2];   // [128]
    float* out = (float*)d_out;

    int total_chunks = out_size / CHUNK;           // 32*128*512 = 2097152
    int threads = 256;
    int blocks = (total_chunks + threads - 1) / threads;
    dwconv1d_kernel<<<blocks, threads>>>(x, weight, bias, out, total_chunks);
}